// round 5
// baseline (speedup 1.0000x reference)
#include <cuda_runtime.h>
#include <cstdint>

// ---------------------------------------------------------------------------
// Problem constants
// ---------------------------------------------------------------------------
#define N_NODES 40000
#define N_EDGES 640000
#define D       128          // IN = HID = OUT = 128
#define DECD    64

// ---------------------------------------------------------------------------
// Scratch (static device globals; no allocations allowed)
// ---------------------------------------------------------------------------
__device__ float  g_h0[N_NODES * D];     // dropout(x)
__device__ float  g_h1[N_NODES * D];     // dropout(relu(layer1))
__device__ float  g_neigh[N_NODES * D];  // segment-sum scratch
__device__ float  g_deg[N_NODES];
__device__ float  g_logits[N_NODES * DECD];
__device__ double g_acc;

// ---------------------------------------------------------------------------
// JAX-exact threefry2x32 (20 rounds). Matches jax._src.prng.threefry2x32.
// ---------------------------------------------------------------------------
__host__ __device__ __forceinline__ void tf2x32(uint32_t k0, uint32_t k1,
                                                uint32_t x0, uint32_t x1,
                                                uint32_t* o0, uint32_t* o1) {
    uint32_t ks2 = k0 ^ k1 ^ 0x1BD11BDAu;
    x0 += k0; x1 += k1;
#define TF_RND(r) { x0 += x1; x1 = (x1 << (r)) | (x1 >> (32 - (r))); x1 ^= x0; }
    TF_RND(13) TF_RND(15) TF_RND(26) TF_RND(6)   x0 += k1;  x1 += ks2 + 1u;
    TF_RND(17) TF_RND(29) TF_RND(16) TF_RND(24)  x0 += ks2; x1 += k0  + 2u;
    TF_RND(13) TF_RND(15) TF_RND(26) TF_RND(6)   x0 += k0;  x1 += k1  + 3u;
    TF_RND(17) TF_RND(29) TF_RND(16) TF_RND(24)  x0 += k1;  x1 += ks2 + 4u;
    TF_RND(13) TF_RND(15) TF_RND(26) TF_RND(6)   x0 += ks2; x1 += k0  + 5u;
#undef TF_RND
    *o0 = x0; *o1 = x1;
}

// Partitionable-mode 32-bit random bits for flat index j (hi word = 0):
// bits = out0 ^ out1 of threefry(key, (0, j)).  keep <=> bit31 == 0.
__device__ __forceinline__ uint32_t pbits(uint32_t k0, uint32_t k1, uint32_t j) {
    uint32_t o0, o1;
    tf2x32(k0, k1, 0u, j, &o0, &o1);
    return o0 ^ o1;
}

// ---------------------------------------------------------------------------
// Kernel 1: dropout on x -> g_h0.  One thread handles 4 contiguous elements.
// ---------------------------------------------------------------------------
__global__ void dropout_x_kernel(const float* __restrict__ x,
                                 uint32_t k0, uint32_t k1) {
    int t = blockIdx.x * blockDim.x + threadIdx.x;
    int j = t * 4;
    if (j >= N_NODES * D) return;
    float4 v = *reinterpret_cast<const float4*>(x + j);
    float4 r;
    r.x = (pbits(k0, k1, j + 0) & 0x80000000u) ? 0.0f : v.x * 2.0f;
    r.y = (pbits(k0, k1, j + 1) & 0x80000000u) ? 0.0f : v.y * 2.0f;
    r.z = (pbits(k0, k1, j + 2) & 0x80000000u) ? 0.0f : v.z * 2.0f;
    r.w = (pbits(k0, k1, j + 3) & 0x80000000u) ? 0.0f : v.w * 2.0f;
    *reinterpret_cast<float4*>(g_h0 + j) = r;
}

// ---------------------------------------------------------------------------
// Kernel 2: edge scatter  neigh[dst] += h[src].  One warp per edge;
// lane handles 4 contiguous floats: float4 gather + one red.global.v4 add.
// DEG=1 also accumulates in-degree (lane 0).
// ---------------------------------------------------------------------------
template <int DEG>
__global__ void scatter_kernel(const float* __restrict__ h,
                               const int* __restrict__ src,
                               const int* __restrict__ dst) {
    int gw   = (blockIdx.x * blockDim.x + threadIdx.x) >> 5;
    int lane = threadIdx.x & 31;
    if (gw >= N_EDGES) return;
    int s = __ldg(&src[gw]);
    int d = __ldg(&dst[gw]);
    float4 v = *reinterpret_cast<const float4*>(h + (size_t)s * D + lane * 4);
    float* o = g_neigh + (size_t)d * D + lane * 4;
#if __CUDA_ARCH__ >= 900
    asm volatile("red.global.add.v4.f32 [%0], {%1, %2, %3, %4};"
                 :: "l"(o), "f"(v.x), "f"(v.y), "f"(v.z), "f"(v.w)
                 : "memory");
#else
    atomicAdd(o + 0, v.x);
    atomicAdd(o + 1, v.y);
    atomicAdd(o + 2, v.z);
    atomicAdd(o + 3, v.w);
#endif
    if (DEG && lane == 0) atomicAdd(&g_deg[d], 1.0f);
}

// ---------------------------------------------------------------------------
// Kernel 3: fused agg + GEMM (+ bias [+ relu + dropout]) for 128x128 layers.
// Block = 128 threads (thread == output column), 16 nodes per block.
// Smem: W padded to row stride 132 floats -> conflict-free LDS.128.
// ---------------------------------------------------------------------------
#define WPAD 132
#define GEMM_SMEM ((128 * WPAD + 16 * WPAD) * 4)

template <int RELU_DROP>
__global__ void gemm_kernel(const float* __restrict__ hin,
                            const float* __restrict__ W,
                            const float* __restrict__ bias,
                            float* __restrict__ out,
                            uint32_t k0, uint32_t k1) {
    extern __shared__ float sm[];
    float* Wsh = sm;                 // [128][132]
    float* Ash = sm + 128 * WPAD;    // [16][132]
    const int tid  = threadIdx.x;    // 0..127
    const int base = blockIdx.x * 16;

    // Load W (row-major [128 out][128 in]) into padded smem
    #pragma unroll
    for (int idx = tid; idx < 128 * 128; idx += 128) {
        int r = idx >> 7, c = idx & 127;
        Wsh[r * WPAD + c] = W[idx];
    }
    // Build agg tile: (hin + neigh) / (deg + 1)
    #pragma unroll
    for (int m = 0; m < 16; m++) {
        int v = base + m;
        float rs = 1.0f / (g_deg[v] + 1.0f);
        Ash[m * WPAD + tid] =
            (hin[(size_t)v * D + tid] + g_neigh[(size_t)v * D + tid]) * rs;
    }
    __syncthreads();

    const int c = tid;
    float acc[16];
    float bc = bias[c];
    #pragma unroll
    for (int n = 0; n < 16; n++) acc[n] = bc;

    const float4* W4 = reinterpret_cast<const float4*>(Wsh); // row stride 33
    const float4* A4 = reinterpret_cast<const float4*>(Ash);
    #pragma unroll
    for (int k4 = 0; k4 < 32; k4++) {
        float4 w = W4[c * 33 + k4];
        #pragma unroll
        for (int n = 0; n < 16; n++) {
            float4 a = A4[n * 33 + k4];
            acc[n] += a.x * w.x + a.y * w.y + a.z * w.z + a.w * w.w;
        }
    }

    #pragma unroll
    for (int n = 0; n < 16; n++) {
        int v = base + n;
        float val = acc[n];
        if (RELU_DROP) {
            val = fmaxf(val, 0.0f);
            uint32_t j = (uint32_t)(v * D + c);     // flat index into (N, 128)
            val = (pbits(k0, k1, j) & 0x80000000u) ? 0.0f : val * 2.0f;
        }
        out[(size_t)v * D + c] = val;
    }
}

// ---------------------------------------------------------------------------
// Kernel 4: logits L = h2 @ Wd^T + bd   (N x 64), K = 128
// Block = 64 threads, 16 nodes/block.
// ---------------------------------------------------------------------------
#define LOGITS_SMEM ((64 * WPAD + 16 * WPAD) * 4)

__global__ void logits_kernel(const float* __restrict__ h2,
                              const float* __restrict__ Wd,
                              const float* __restrict__ bd) {
    extern __shared__ float sm[];
    float* Wsh = sm;               // [64][132]
    float* Ash = sm + 64 * WPAD;   // [16][132]
    const int tid  = threadIdx.x;  // 0..63
    const int base = blockIdx.x * 16;

    for (int idx = tid; idx < 64 * 128; idx += 64) {
        int r = idx >> 7, c = idx & 127;
        Wsh[r * WPAD + c] = Wd[idx];
    }
    for (int idx = tid; idx < 16 * 128; idx += 64) {
        int n = idx >> 7, c = idx & 127;
        Ash[n * WPAD + c] = h2[(size_t)(base + n) * D + c];
    }
    __syncthreads();

    const int c = tid;
    float acc[16];
    float bc = bd[c];
    #pragma unroll
    for (int n = 0; n < 16; n++) acc[n] = bc;

    const float4* W4 = reinterpret_cast<const float4*>(Wsh);
    const float4* A4 = reinterpret_cast<const float4*>(Ash);
    #pragma unroll
    for (int k4 = 0; k4 < 32; k4++) {
        float4 w = W4[c * 33 + k4];
        #pragma unroll
        for (int n = 0; n < 16; n++) {
            float4 a = A4[n * 33 + k4];
            acc[n] += a.x * w.x + a.y * w.y + a.z * w.z + a.w * w.w;
        }
    }
    #pragma unroll
    for (int n = 0; n < 16; n++)
        g_logits[(size_t)(base + n) * DECD + c] = acc[n];
}

// ---------------------------------------------------------------------------
// Kernel 5: decoder loss.  One warp per node; lane covers cols (l, l+32).
// loss_v = -(sum_d L[shuf[v]][d] * (L[v][d] - logsumexp(L[v])))
// ---------------------------------------------------------------------------
__global__ void dec_kernel(const int* __restrict__ shuf) {
    __shared__ float warp_sums[8];
    int warp = threadIdx.x >> 5;
    int lane = threadIdx.x & 31;
    int v = blockIdx.x * 8 + warp;
    float contrib = 0.0f;
    if (v < N_NODES) {
        const float* a = g_logits + (size_t)v * DECD;
        float a0 = a[lane], a1 = a[lane + 32];
        float m = fmaxf(a0, a1);
        #pragma unroll
        for (int off = 16; off; off >>= 1)
            m = fmaxf(m, __shfl_xor_sync(0xffffffffu, m, off));
        float s = expf(a0 - m) + expf(a1 - m);
        #pragma unroll
        for (int off = 16; off; off >>= 1)
            s += __shfl_xor_sync(0xffffffffu, s, off);
        float lse = m + logf(s);
        const float* bp = g_logits + (size_t)__ldg(&shuf[v]) * DECD;
        float b0 = bp[lane], b1 = bp[lane + 32];
        float t = b0 * (a0 - lse) + b1 * (a1 - lse);
        #pragma unroll
        for (int off = 16; off; off >>= 1)
            t += __shfl_xor_sync(0xffffffffu, t, off);
        contrib = -t;
    }
    if (lane == 0) warp_sums[warp] = contrib;
    __syncthreads();
    if (threadIdx.x == 0) {
        float s = 0.0f;
        #pragma unroll
        for (int w = 0; w < 8; w++) s += warp_sums[w];
        atomicAdd(&g_acc, (double)s);
    }
}

__global__ void finalize_kernel(float* __restrict__ out) {
    out[(size_t)N_NODES * D] = (float)(g_acc / (double)N_NODES);
}

// ---------------------------------------------------------------------------
// Host launcher (graph-capturable: kernels + async memsets only)
// ---------------------------------------------------------------------------
extern "C" void kernel_launch(void* const* d_in, const int* in_sizes, int n_in,
                              void* d_out, int out_size) {
    const float* x    = (const float*)d_in[0];
    const int*   src  = (const int*)  d_in[1];
    const int*   dst  = (const int*)  d_in[2];
    const int*   shuf = (const int*)  d_in[3];
    const float* W1   = (const float*)d_in[4];
    const float* b1   = (const float*)d_in[5];
    const float* W2   = (const float*)d_in[6];
    const float* b2   = (const float*)d_in[7];
    const float* Wd   = (const float*)d_in[8];
    const float* bd   = (const float*)d_in[9];
    float* out = (float*)d_out;

    // JAX partitionable threefry (default since jax 0.4.36):
    // split(key(42), 2) is "foldlike": key_i = both outputs of
    // threefry([0,42], counter=(hi=0, lo=i)).
    uint32_t dk0_k0, dk0_k1, dk1_k0, dk1_k1;
    tf2x32(0u, 42u, 0u, 0u, &dk0_k0, &dk0_k1);   // dropout on x
    tf2x32(0u, 42u, 0u, 1u, &dk1_k0, &dk1_k1);   // dropout after relu(layer1)

    void *p_neigh, *p_deg, *p_acc, *p_h0, *p_h1;
    cudaGetSymbolAddress(&p_neigh, g_neigh);
    cudaGetSymbolAddress(&p_deg,   g_deg);
    cudaGetSymbolAddress(&p_acc,   g_acc);
    cudaGetSymbolAddress(&p_h0,    g_h0);
    cudaGetSymbolAddress(&p_h1,    g_h1);

    cudaFuncSetAttribute(gemm_kernel<1>, cudaFuncAttributeMaxDynamicSharedMemorySize, GEMM_SMEM);
    cudaFuncSetAttribute(gemm_kernel<0>, cudaFuncAttributeMaxDynamicSharedMemorySize, GEMM_SMEM);
    cudaFuncSetAttribute(logits_kernel,  cudaFuncAttributeMaxDynamicSharedMemorySize, LOGITS_SMEM);

    // Zero accumulators
    cudaMemsetAsync(p_deg,   0, N_NODES * sizeof(float));
    cudaMemsetAsync(p_neigh, 0, (size_t)N_NODES * D * sizeof(float));
    cudaMemsetAsync(p_acc,   0, sizeof(double));

    // h0 = dropout(x, dk0)
    dropout_x_kernel<<<(N_NODES * D / 4 + 255) / 256, 256>>>(x, dk0_k0, dk0_k1);

    // layer 1: scatter (+degree) + fused agg/GEMM/relu/dropout -> g_h1
    scatter_kernel<1><<<(N_EDGES * 32) / 256, 256>>>((const float*)p_h0, src, dst);
    gemm_kernel<1><<<N_NODES / 16, 128, GEMM_SMEM>>>(
        (const float*)p_h0, W1, b1, (float*)p_h1, dk1_k0, dk1_k1);

    // layer 2: re-zero neigh, scatter, GEMM -> d_out (h)
    cudaMemsetAsync(p_neigh, 0, (size_t)N_NODES * D * sizeof(float));
    scatter_kernel<0><<<(N_EDGES * 32) / 256, 256>>>((const float*)p_h1, src, dst);
    gemm_kernel<0><<<N_NODES / 16, 128, GEMM_SMEM>>>(
        (const float*)p_h1, W2, b2, out, 0u, 0u);

    // decoder
    logits_kernel<<<N_NODES / 16, 64, LOGITS_SMEM>>>(out, Wd, bd);
    dec_kernel<<<N_NODES / 8, 256>>>(shuf);
    finalize_kernel<<<1, 1>>>(out);
}

// round 6
// speedup vs baseline: 1.4072x; 1.4072x over previous
#include <cuda_runtime.h>
#include <cstdint>

// ---------------------------------------------------------------------------
// Problem constants
// ---------------------------------------------------------------------------
#define N_NODES 40000
#define N_EDGES 640000
#define D       128          // IN = HID = OUT = 128
#define DECD    64

// ---------------------------------------------------------------------------
// Scratch (static device globals; no allocations allowed)
// ---------------------------------------------------------------------------
__device__ float  g_h0[N_NODES * D];       // dropout(x)
__device__ float  g_h1[N_NODES * D];       // dropout(relu(layer1))
__device__ float  g_agg[N_NODES * D];      // normalized aggregate (GEMM input)
__device__ float  g_logits[N_NODES * DECD];
__device__ int    g_degi[N_NODES];
__device__ int    g_rowptr[N_NODES + 1];
__device__ int    g_cursor[N_NODES];
__device__ int    g_esrc[N_EDGES];         // CSR-permuted source ids
__device__ double g_acc;

// ---------------------------------------------------------------------------
// JAX-exact threefry2x32 (20 rounds), partitionable mode.
// ---------------------------------------------------------------------------
__host__ __device__ __forceinline__ void tf2x32(uint32_t k0, uint32_t k1,
                                                uint32_t x0, uint32_t x1,
                                                uint32_t* o0, uint32_t* o1) {
    uint32_t ks2 = k0 ^ k1 ^ 0x1BD11BDAu;
    x0 += k0; x1 += k1;
#define TF_RND(r) { x0 += x1; x1 = (x1 << (r)) | (x1 >> (32 - (r))); x1 ^= x0; }
    TF_RND(13) TF_RND(15) TF_RND(26) TF_RND(6)   x0 += k1;  x1 += ks2 + 1u;
    TF_RND(17) TF_RND(29) TF_RND(16) TF_RND(24)  x0 += ks2; x1 += k0  + 2u;
    TF_RND(13) TF_RND(15) TF_RND(26) TF_RND(6)   x0 += k0;  x1 += k1  + 3u;
    TF_RND(17) TF_RND(29) TF_RND(16) TF_RND(24)  x0 += k1;  x1 += ks2 + 4u;
    TF_RND(13) TF_RND(15) TF_RND(26) TF_RND(6)   x0 += ks2; x1 += k0  + 5u;
#undef TF_RND
    *o0 = x0; *o1 = x1;
}

// bits = out0 ^ out1 of threefry(key, (0, j)).  keep <=> bit31 == 0.
__device__ __forceinline__ uint32_t pbits(uint32_t k0, uint32_t k1, uint32_t j) {
    uint32_t o0, o1;
    tf2x32(k0, k1, 0u, j, &o0, &o1);
    return o0 ^ o1;
}

// ---------------------------------------------------------------------------
// Packed f32x2 helpers (Blackwell): one FFMA2 = two independent fp32 FMAs.
// ---------------------------------------------------------------------------
__device__ __forceinline__ unsigned long long pk2(float lo, float hi) {
    unsigned long long r;
    asm("mov.b64 %0, {%1, %2};" : "=l"(r) : "f"(lo), "f"(hi));
    return r;
}
__device__ __forceinline__ void upk2(unsigned long long v, float& lo, float& hi) {
    asm("mov.b64 {%0, %1}, %2;" : "=f"(lo), "=f"(hi) : "l"(v));
}
__device__ __forceinline__ void fma2(unsigned long long& d,
                                     unsigned long long a,
                                     unsigned long long b) {
    asm("fma.rn.f32x2 %0, %1, %2, %0;" : "+l"(d) : "l"(a), "l"(b));
}

// ---------------------------------------------------------------------------
// Kernel: dropout on x -> g_h0
// ---------------------------------------------------------------------------
__global__ void dropout_x_kernel(const float* __restrict__ x,
                                 uint32_t k0, uint32_t k1) {
    int t = blockIdx.x * blockDim.x + threadIdx.x;
    int j = t * 4;
    if (j >= N_NODES * D) return;
    float4 v = *reinterpret_cast<const float4*>(x + j);
    float4 r;
    r.x = (pbits(k0, k1, j + 0) & 0x80000000u) ? 0.0f : v.x * 2.0f;
    r.y = (pbits(k0, k1, j + 1) & 0x80000000u) ? 0.0f : v.y * 2.0f;
    r.z = (pbits(k0, k1, j + 2) & 0x80000000u) ? 0.0f : v.z * 2.0f;
    r.w = (pbits(k0, k1, j + 3) & 0x80000000u) ? 0.0f : v.w * 2.0f;
    *reinterpret_cast<float4*>(g_h0 + j) = r;
}

// ---------------------------------------------------------------------------
// CSR build: degree count, single-block scan, slot fill
// ---------------------------------------------------------------------------
__global__ void deg_kernel(const int* __restrict__ dst) {
    int e = blockIdx.x * blockDim.x + threadIdx.x;
    if (e < N_EDGES) atomicAdd(&g_degi[__ldg(&dst[e])], 1);
}

__global__ void scan_kernel() {
    // 1024 threads; thread t owns nodes [t*40, t*40+40); 1000 active chunks.
    __shared__ int sh[1024];
    const int tid = threadIdx.x;
    const int per = 40;
    int base = tid * per;
    int s = 0;
    if (base < N_NODES)
        for (int i = 0; i < per; i++) s += g_degi[base + i];
    sh[tid] = s;
    __syncthreads();
    // Hillis-Steele inclusive scan
    for (int o = 1; o < 1024; o <<= 1) {
        int v = (tid >= o) ? sh[tid - o] : 0;
        __syncthreads();
        sh[tid] += v;
        __syncthreads();
    }
    int run = (tid > 0) ? sh[tid - 1] : 0;   // exclusive prefix
    if (base < N_NODES) {
        for (int i = 0; i < per; i++) {
            int v = base + i;
            g_rowptr[v] = run;
            g_cursor[v] = run;
            run += g_degi[v];
        }
        if (base + per >= N_NODES) g_rowptr[N_NODES] = run;
    }
}

__global__ void fill_kernel(const int* __restrict__ src,
                            const int* __restrict__ dst) {
    int e = blockIdx.x * blockDim.x + threadIdx.x;
    if (e >= N_EDGES) return;
    int d = __ldg(&dst[e]);
    int slot = atomicAdd(&g_cursor[d], 1);
    g_esrc[slot] = __ldg(&src[e]);
}

// ---------------------------------------------------------------------------
// Aggregate: one warp per node.  agg[v] = (h[v] + sum_{u->v} h[u]) / (deg+1)
// lane handles 4 contiguous floats (float4).
// ---------------------------------------------------------------------------
__global__ void agg_kernel(const float* __restrict__ h) {
    int w    = (blockIdx.x * blockDim.x + threadIdx.x) >> 5;
    int lane = threadIdx.x & 31;
    if (w >= N_NODES) return;
    const int beg = __ldg(&g_rowptr[w]);
    const int end = __ldg(&g_rowptr[w + 1]);
    float4 acc = *reinterpret_cast<const float4*>(h + (size_t)w * D + lane * 4);
    int i = beg;
    for (; i + 1 < end; i += 2) {
        int s0 = __ldg(&g_esrc[i]);
        int s1 = __ldg(&g_esrc[i + 1]);
        float4 m0 = *reinterpret_cast<const float4*>(h + (size_t)s0 * D + lane * 4);
        float4 m1 = *reinterpret_cast<const float4*>(h + (size_t)s1 * D + lane * 4);
        acc.x += m0.x; acc.y += m0.y; acc.z += m0.z; acc.w += m0.w;
        acc.x += m1.x; acc.y += m1.y; acc.z += m1.z; acc.w += m1.w;
    }
    if (i < end) {
        int s0 = __ldg(&g_esrc[i]);
        float4 m0 = *reinterpret_cast<const float4*>(h + (size_t)s0 * D + lane * 4);
        acc.x += m0.x; acc.y += m0.y; acc.z += m0.z; acc.w += m0.w;
    }
    float rs = 1.0f / (float)(end - beg + 1);
    acc.x *= rs; acc.y *= rs; acc.z *= rs; acc.w *= rs;
    *reinterpret_cast<float4*>(g_agg + (size_t)w * D + lane * 4) = acc;
}

// ---------------------------------------------------------------------------
// Register-tiled GEMM:  out[v][c] = sum_k agg[v][k] * W[c][k] + bias[c]
// Tile: 32 nodes x NC cols.  Threads: (NC/4) x 8.  Microtile: 4 nodes x 4 cols.
// Accumulators packed as f32x2 over node pairs -> fma.rn.f32x2.
// smem: Wt[k][c] transposed, stride NCP (conflict-free LDS.128);
//       AshP node-pair-interleaved (broadcast LDS.64).
// ---------------------------------------------------------------------------
template <int NC, int RELU_DROP>
__global__ void __launch_bounds__((NC / 4) * 8)
gemm_tiled_kernel(const float* __restrict__ A,
                  const float* __restrict__ W,
                  const float* __restrict__ bias,
                  float* __restrict__ out,
                  uint32_t k0, uint32_t k1) {
    constexpr int NCP  = NC + 4;       // padded Wt row stride (floats)
    constexpr int TXN  = NC / 4;       // threads along cols
    constexpr int NTHR = TXN * 8;
    extern __shared__ float sm[];
    float* Wt   = sm;                  // [128][NCP]
    float* AshF = sm + 128 * NCP;      // [16 pairs][128 k][2] floats
    const unsigned long long* AshU =
        reinterpret_cast<const unsigned long long*>(AshF);

    const int tid  = threadIdx.x;
    const int tx   = tid % TXN;        // col group: cols 4*tx .. 4*tx+3
    const int ty   = tid / TXN;        // node group: nodes 4*ty .. 4*ty+3
    const int base = blockIdx.x * 32;

    // Load W [NC][128] row-major -> transposed padded smem Wt[k][c]
    for (int idx = tid; idx < NC * 128; idx += NTHR) {
        int c = idx >> 7, k = idx & 127;
        Wt[k * NCP + c] = W[idx];
    }
    // Load A tile (32 rows) -> node-pair-interleaved
    for (int idx = tid; idx < 32 * 128; idx += NTHR) {
        int n = idx >> 7, k = idx & 127;
        AshF[(n >> 1) * 256 + 2 * k + (n & 1)] = A[(size_t)(base + n) * D + k];
    }
    __syncthreads();

    unsigned long long acc2[2][4];
    #pragma unroll
    for (int p = 0; p < 2; p++)
        #pragma unroll
        for (int j = 0; j < 4; j++) acc2[p][j] = 0ull;

    const int p0 = ty * 2;             // pair rows p0, p0+1
    #pragma unroll 8
    for (int k = 0; k < 128; k += 4) {
        float4 wv[4];
        #pragma unroll
        for (int i = 0; i < 4; i++)
            wv[i] = *reinterpret_cast<const float4*>(&Wt[(k + i) * NCP + 4 * tx]);
        unsigned long long a2[2][4];
        #pragma unroll
        for (int p = 0; p < 2; p++)
            #pragma unroll
            for (int i = 0; i < 4; i++)
                a2[p][i] = AshU[(p0 + p) * 128 + k + i];
        #pragma unroll
        for (int i = 0; i < 4; i++) {
            unsigned long long wd0 = pk2(wv[i].x, wv[i].x);
            unsigned long long wd1 = pk2(wv[i].y, wv[i].y);
            unsigned long long wd2 = pk2(wv[i].z, wv[i].z);
            unsigned long long wd3 = pk2(wv[i].w, wv[i].w);
            fma2(acc2[0][0], a2[0][i], wd0);
            fma2(acc2[1][0], a2[1][i], wd0);
            fma2(acc2[0][1], a2[0][i], wd1);
            fma2(acc2[1][1], a2[1][i], wd1);
            fma2(acc2[0][2], a2[0][i], wd2);
            fma2(acc2[1][2], a2[1][i], wd2);
            fma2(acc2[0][3], a2[0][i], wd3);
            fma2(acc2[1][3], a2[1][i], wd3);
        }
    }

    // Epilogue
    float bias4[4];
    #pragma unroll
    for (int j = 0; j < 4; j++) bias4[j] = __ldg(&bias[4 * tx + j]);

    #pragma unroll
    for (int p = 0; p < 2; p++) {
        float lo[4], hi[4];
        #pragma unroll
        for (int j = 0; j < 4; j++) upk2(acc2[p][j], lo[j], hi[j]);
        #pragma unroll
        for (int half = 0; half < 2; half++) {
            int n = ty * 4 + 2 * p + half;
            int v = base + n;
            float4 r;
            float* vals = half ? hi : lo;
            r.x = vals[0] + bias4[0];
            r.y = vals[1] + bias4[1];
            r.z = vals[2] + bias4[2];
            r.w = vals[3] + bias4[3];
            if (RELU_DROP) {
                r.x = fmaxf(r.x, 0.0f); r.y = fmaxf(r.y, 0.0f);
                r.z = fmaxf(r.z, 0.0f); r.w = fmaxf(r.w, 0.0f);
                uint32_t j0 = (uint32_t)(v * D + 4 * tx);
                r.x = (pbits(k0, k1, j0 + 0) & 0x80000000u) ? 0.0f : r.x * 2.0f;
                r.y = (pbits(k0, k1, j0 + 1) & 0x80000000u) ? 0.0f : r.y * 2.0f;
                r.z = (pbits(k0, k1, j0 + 2) & 0x80000000u) ? 0.0f : r.z * 2.0f;
                r.w = (pbits(k0, k1, j0 + 3) & 0x80000000u) ? 0.0f : r.w * 2.0f;
            }
            *reinterpret_cast<float4*>(out + (size_t)v * NC + 4 * tx) = r;
        }
    }
}

#define GEMM128_SMEM ((128 * 132 + 16 * 256) * 4)
#define GEMM64_SMEM  ((128 * 68  + 16 * 256) * 4)

// ---------------------------------------------------------------------------
// Decoder loss.  One warp per node; lane covers cols (l, l+32).
// ---------------------------------------------------------------------------
__global__ void dec_kernel(const int* __restrict__ shuf) {
    __shared__ float warp_sums[8];
    int warp = threadIdx.x >> 5;
    int lane = threadIdx.x & 31;
    int v = blockIdx.x * 8 + warp;
    float contrib = 0.0f;
    if (v < N_NODES) {
        const float* a = g_logits + (size_t)v * DECD;
        float a0 = a[lane], a1 = a[lane + 32];
        float m = fmaxf(a0, a1);
        #pragma unroll
        for (int off = 16; off; off >>= 1)
            m = fmaxf(m, __shfl_xor_sync(0xffffffffu, m, off));
        float s = expf(a0 - m) + expf(a1 - m);
        #pragma unroll
        for (int off = 16; off; off >>= 1)
            s += __shfl_xor_sync(0xffffffffu, s, off);
        float lse = m + logf(s);
        const float* bp = g_logits + (size_t)__ldg(&shuf[v]) * DECD;
        float b0 = bp[lane], b1 = bp[lane + 32];
        float t = b0 * (a0 - lse) + b1 * (a1 - lse);
        #pragma unroll
        for (int off = 16; off; off >>= 1)
            t += __shfl_xor_sync(0xffffffffu, t, off);
        contrib = -t;
    }
    if (lane == 0) warp_sums[warp] = contrib;
    __syncthreads();
    if (threadIdx.x == 0) {
        float s = 0.0f;
        #pragma unroll
        for (int w = 0; w < 8; w++) s += warp_sums[w];
        atomicAdd(&g_acc, (double)s);
    }
}

__global__ void finalize_kernel(float* __restrict__ out) {
    out[(size_t)N_NODES * D] = (float)(g_acc / (double)N_NODES);
}

// ---------------------------------------------------------------------------
// Host launcher (graph-capturable)
// ---------------------------------------------------------------------------
extern "C" void kernel_launch(void* const* d_in, const int* in_sizes, int n_in,
                              void* d_out, int out_size) {
    const float* x    = (const float*)d_in[0];
    const int*   src  = (const int*)  d_in[1];
    const int*   dst  = (const int*)  d_in[2];
    const int*   shuf = (const int*)  d_in[3];
    const float* W1   = (const float*)d_in[4];
    const float* b1   = (const float*)d_in[5];
    const float* W2   = (const float*)d_in[6];
    const float* b2   = (const float*)d_in[7];
    const float* Wd   = (const float*)d_in[8];
    const float* bd   = (const float*)d_in[9];
    float* out = (float*)d_out;

    // JAX partitionable threefry: split(key(42),2) foldlike.
    uint32_t dk0_k0, dk0_k1, dk1_k0, dk1_k1;
    tf2x32(0u, 42u, 0u, 0u, &dk0_k0, &dk0_k1);   // dropout on x
    tf2x32(0u, 42u, 0u, 1u, &dk1_k0, &dk1_k1);   // dropout after relu(layer1)

    void *p_degi, *p_acc, *p_h0, *p_h1, *p_agg, *p_logits;
    cudaGetSymbolAddress(&p_degi,   g_degi);
    cudaGetSymbolAddress(&p_acc,    g_acc);
    cudaGetSymbolAddress(&p_h0,     g_h0);
    cudaGetSymbolAddress(&p_h1,     g_h1);
    cudaGetSymbolAddress(&p_agg,    g_agg);
    cudaGetSymbolAddress(&p_logits, g_logits);

    cudaFuncSetAttribute((const void*)gemm_tiled_kernel<128, 1>,
                         cudaFuncAttributeMaxDynamicSharedMemorySize, GEMM128_SMEM);
    cudaFuncSetAttribute((const void*)gemm_tiled_kernel<128, 0>,
                         cudaFuncAttributeMaxDynamicSharedMemorySize, GEMM128_SMEM);
    cudaFuncSetAttribute((const void*)gemm_tiled_kernel<64, 0>,
                         cudaFuncAttributeMaxDynamicSharedMemorySize, GEMM64_SMEM);

    // Zero accumulators
    cudaMemsetAsync(p_degi, 0, N_NODES * sizeof(int));
    cudaMemsetAsync(p_acc,  0, sizeof(double));

    // CSR build (reused by both layers)
    deg_kernel<<<(N_EDGES + 255) / 256, 256>>>(dst);
    scan_kernel<<<1, 1024>>>();
    fill_kernel<<<(N_EDGES + 255) / 256, 256>>>(src, dst);

    // h0 = dropout(x, dk0)
    dropout_x_kernel<<<(N_NODES * D / 4 + 255) / 256, 256>>>(x, dk0_k0, dk0_k1);

    // layer 1
    agg_kernel<<<(N_NODES * 32) / 256, 256>>>((const float*)p_h0);
    gemm_tiled_kernel<128, 1><<<N_NODES / 32, 256, GEMM128_SMEM>>>(
        (const float*)p_agg, W1, b1, (float*)p_h1, dk1_k0, dk1_k1);

    // layer 2
    agg_kernel<<<(N_NODES * 32) / 256, 256>>>((const float*)p_h1);
    gemm_tiled_kernel<128, 0><<<N_NODES / 32, 256, GEMM128_SMEM>>>(
        (const float*)p_agg, W2, b2, out, 0u, 0u);

    // decoder
    gemm_tiled_kernel<64, 0><<<N_NODES / 32, 128, GEMM64_SMEM>>>(
        out, Wd, bd, (float*)p_logits, 0u, 0u);
    dec_kernel<<<N_NODES / 8, 256>>>(shuf);
    finalize_kernel<<<1, 1>>>(out);
}

// round 7
// speedup vs baseline: 1.4910x; 1.0595x over previous
#include <cuda_runtime.h>
#include <cstdint>

// ---------------------------------------------------------------------------
// Problem constants
// ---------------------------------------------------------------------------
#define N_NODES 40000
#define N_EDGES 640000
#define D       128          // IN = HID = OUT = 128
#define DECD    64

// ---------------------------------------------------------------------------
// Scratch (static device globals; no allocations allowed)
// ---------------------------------------------------------------------------
__device__ float  g_h0[N_NODES * D];       // dropout(x)
__device__ float  g_h1[N_NODES * D];       // dropout(relu(layer1))
__device__ float  g_logits[N_NODES * DECD];
__device__ int    g_degi[N_NODES];
__device__ int    g_rowptr[N_NODES + 1];
__device__ int    g_cursor[N_NODES];
__device__ int    g_esrc[N_EDGES];         // CSR-permuted source ids
__device__ double g_acc;

// ---------------------------------------------------------------------------
// JAX-exact threefry2x32 (20 rounds), partitionable mode.
// ---------------------------------------------------------------------------
__host__ __device__ __forceinline__ void tf2x32(uint32_t k0, uint32_t k1,
                                                uint32_t x0, uint32_t x1,
                                                uint32_t* o0, uint32_t* o1) {
    uint32_t ks2 = k0 ^ k1 ^ 0x1BD11BDAu;
    x0 += k0; x1 += k1;
#define TF_RND(r) { x0 += x1; x1 = (x1 << (r)) | (x1 >> (32 - (r))); x1 ^= x0; }
    TF_RND(13) TF_RND(15) TF_RND(26) TF_RND(6)   x0 += k1;  x1 += ks2 + 1u;
    TF_RND(17) TF_RND(29) TF_RND(16) TF_RND(24)  x0 += ks2; x1 += k0  + 2u;
    TF_RND(13) TF_RND(15) TF_RND(26) TF_RND(6)   x0 += k0;  x1 += k1  + 3u;
    TF_RND(17) TF_RND(29) TF_RND(16) TF_RND(24)  x0 += k1;  x1 += ks2 + 4u;
    TF_RND(13) TF_RND(15) TF_RND(26) TF_RND(6)   x0 += ks2; x1 += k0  + 5u;
#undef TF_RND
    *o0 = x0; *o1 = x1;
}

// bits = out0 ^ out1 of threefry(key, (0, j)).  keep <=> bit31 == 0.
__device__ __forceinline__ uint32_t pbits(uint32_t k0, uint32_t k1, uint32_t j) {
    uint32_t o0, o1;
    tf2x32(k0, k1, 0u, j, &o0, &o1);
    return o0 ^ o1;
}

// ---------------------------------------------------------------------------
// Packed f32x2 helpers (Blackwell FFMA2)
// ---------------------------------------------------------------------------
__device__ __forceinline__ unsigned long long pk2(float lo, float hi) {
    unsigned long long r;
    asm("mov.b64 %0, {%1, %2};" : "=l"(r) : "f"(lo), "f"(hi));
    return r;
}
__device__ __forceinline__ void upk2(unsigned long long v, float& lo, float& hi) {
    asm("mov.b64 {%0, %1}, %2;" : "=f"(lo), "=f"(hi) : "l"(v));
}
__device__ __forceinline__ void fma2(unsigned long long& d,
                                     unsigned long long a,
                                     unsigned long long b) {
    asm("fma.rn.f32x2 %0, %1, %2, %0;" : "+l"(d) : "l"(a), "l"(b));
}

// ---------------------------------------------------------------------------
// dropout on x -> g_h0
// ---------------------------------------------------------------------------
__global__ void dropout_x_kernel(const float* __restrict__ x,
                                 uint32_t k0, uint32_t k1) {
    int t = blockIdx.x * blockDim.x + threadIdx.x;
    int j = t * 4;
    if (j >= N_NODES * D) return;
    float4 v = *reinterpret_cast<const float4*>(x + j);
    float4 r;
    r.x = (pbits(k0, k1, j + 0) & 0x80000000u) ? 0.0f : v.x * 2.0f;
    r.y = (pbits(k0, k1, j + 1) & 0x80000000u) ? 0.0f : v.y * 2.0f;
    r.z = (pbits(k0, k1, j + 2) & 0x80000000u) ? 0.0f : v.z * 2.0f;
    r.w = (pbits(k0, k1, j + 3) & 0x80000000u) ? 0.0f : v.w * 2.0f;
    *reinterpret_cast<float4*>(g_h0 + j) = r;
}

// ---------------------------------------------------------------------------
// CSR build: degree count, single-block scan, slot fill
// ---------------------------------------------------------------------------
__global__ void deg_kernel(const int* __restrict__ dst) {
    int e = blockIdx.x * blockDim.x + threadIdx.x;
    if (e < N_EDGES) atomicAdd(&g_degi[__ldg(&dst[e])], 1);
}

__global__ void scan_kernel() {
    __shared__ int sh[1024];
    const int tid = threadIdx.x;
    const int per = 40;
    int base = tid * per;
    int s = 0;
    if (base < N_NODES)
        for (int i = 0; i < per; i++) s += g_degi[base + i];
    sh[tid] = s;
    __syncthreads();
    for (int o = 1; o < 1024; o <<= 1) {
        int v = (tid >= o) ? sh[tid - o] : 0;
        __syncthreads();
        sh[tid] += v;
        __syncthreads();
    }
    int run = (tid > 0) ? sh[tid - 1] : 0;
    if (base < N_NODES) {
        for (int i = 0; i < per; i++) {
            int v = base + i;
            g_rowptr[v] = run;
            g_cursor[v] = run;
            run += g_degi[v];
        }
        if (base + per >= N_NODES) g_rowptr[N_NODES] = run;
    }
}

__global__ void fill_kernel(const int* __restrict__ src,
                            const int* __restrict__ dst) {
    int e = blockIdx.x * blockDim.x + threadIdx.x;
    if (e >= N_EDGES) return;
    int d = __ldg(&dst[e]);
    int slot = atomicAdd(&g_cursor[d], 1);
    g_esrc[slot] = __ldg(&src[e]);
}

// ---------------------------------------------------------------------------
// FUSED layer kernel:  out = fc((h[v] + sum_{u->v} h[u]) / (deg+1))
//                       [+ relu + dropout if RELU_DROP]
// Block = 256 threads, 32 nodes.  Phase A: warp-per-4-nodes CSR gather into
// node-pair-interleaved smem A-tile.  Phase B: 4x4 microtile FFMA2 GEMM.
// smem: Wt[128][132] transposed/padded (67.6 KB) + Ash 16 KB = 84 KB.
// ---------------------------------------------------------------------------
#define FUSED_SMEM ((128 * 132 + 16 * 256) * 4)

template <int RELU_DROP>
__global__ void __launch_bounds__(256)
fused_layer_kernel(const float* __restrict__ h,
                   const float* __restrict__ W,
                   const float* __restrict__ bias,
                   float* __restrict__ out,
                   uint32_t k0, uint32_t k1) {
    extern __shared__ float sm[];
    float* Wt   = sm;                  // [128 k][132] (Wt[k][c] = W[c][k])
    float* AshF = sm + 128 * 132;      // [16 pairs][128 k][2]
    const unsigned long long* AshU =
        reinterpret_cast<const unsigned long long*>(AshF);

    const int tid  = threadIdx.x;
    const int wid  = tid >> 5;         // 0..7
    const int lane = tid & 31;
    const int base = blockIdx.x * 32;

    // --- W load: [128 c][128 k] row-major -> transposed padded smem ---
    #pragma unroll
    for (int idx = tid; idx < 128 * 128; idx += 256) {
        int c = idx >> 7, k = idx & 127;
        Wt[k * 132 + c] = W[idx];
    }

    // --- Phase A: gather 4 nodes per warp; lane covers k = 4*lane..4*lane+3
    #pragma unroll
    for (int nn = 0; nn < 4; nn++) {
        const int n = wid * 4 + nn;
        const int v = base + n;
        const int beg = __ldg(&g_rowptr[v]);
        const int end = __ldg(&g_rowptr[v + 1]);
        float4 acc = *reinterpret_cast<const float4*>(h + (size_t)v * D + lane * 4);
        int i = beg;
        for (; i + 3 < end; i += 4) {
            int s0 = __ldg(&g_esrc[i + 0]);
            int s1 = __ldg(&g_esrc[i + 1]);
            int s2 = __ldg(&g_esrc[i + 2]);
            int s3 = __ldg(&g_esrc[i + 3]);
            float4 m0 = *reinterpret_cast<const float4*>(h + (size_t)s0 * D + lane * 4);
            float4 m1 = *reinterpret_cast<const float4*>(h + (size_t)s1 * D + lane * 4);
            float4 m2 = *reinterpret_cast<const float4*>(h + (size_t)s2 * D + lane * 4);
            float4 m3 = *reinterpret_cast<const float4*>(h + (size_t)s3 * D + lane * 4);
            acc.x += m0.x + m1.x + m2.x + m3.x;
            acc.y += m0.y + m1.y + m2.y + m3.y;
            acc.z += m0.z + m1.z + m2.z + m3.z;
            acc.w += m0.w + m1.w + m2.w + m3.w;
        }
        for (; i < end; i++) {
            int s0 = __ldg(&g_esrc[i]);
            float4 m0 = *reinterpret_cast<const float4*>(h + (size_t)s0 * D + lane * 4);
            acc.x += m0.x; acc.y += m0.y; acc.z += m0.z; acc.w += m0.w;
        }
        float rs = 1.0f / (float)(end - beg + 1);
        acc.x *= rs; acc.y *= rs; acc.z *= rs; acc.w *= rs;
        // store node-pair-interleaved: AshF[(n>>1)*256 + 2k + (n&1)]
        float* p = AshF + (n >> 1) * 256 + (n & 1);
        p[2 * (4 * lane + 0)] = acc.x;
        p[2 * (4 * lane + 1)] = acc.y;
        p[2 * (4 * lane + 2)] = acc.z;
        p[2 * (4 * lane + 3)] = acc.w;
    }
    __syncthreads();

    // --- Phase B: GEMM.  tx = col group (4 cols), ty = node group (4 nodes)
    const int tx = tid & 31;           // cols 4*tx .. 4*tx+3
    const int ty = tid >> 5;           // nodes 4*ty .. 4*ty+3
    unsigned long long acc2[2][4];
    #pragma unroll
    for (int p = 0; p < 2; p++)
        #pragma unroll
        for (int j = 0; j < 4; j++) acc2[p][j] = 0ull;

    const int p0 = ty * 2;
    #pragma unroll 8
    for (int k = 0; k < 128; k += 4) {
        float4 wv[4];
        #pragma unroll
        for (int i = 0; i < 4; i++)
            wv[i] = *reinterpret_cast<const float4*>(&Wt[(k + i) * 132 + 4 * tx]);
        unsigned long long a2[2][4];
        #pragma unroll
        for (int p = 0; p < 2; p++)
            #pragma unroll
            for (int i = 0; i < 4; i++)
                a2[p][i] = AshU[(p0 + p) * 128 + k + i];
        #pragma unroll
        for (int i = 0; i < 4; i++) {
            unsigned long long wd0 = pk2(wv[i].x, wv[i].x);
            unsigned long long wd1 = pk2(wv[i].y, wv[i].y);
            unsigned long long wd2 = pk2(wv[i].z, wv[i].z);
            unsigned long long wd3 = pk2(wv[i].w, wv[i].w);
            fma2(acc2[0][0], a2[0][i], wd0);
            fma2(acc2[1][0], a2[1][i], wd0);
            fma2(acc2[0][1], a2[0][i], wd1);
            fma2(acc2[1][1], a2[1][i], wd1);
            fma2(acc2[0][2], a2[0][i], wd2);
            fma2(acc2[1][2], a2[1][i], wd2);
            fma2(acc2[0][3], a2[0][i], wd3);
            fma2(acc2[1][3], a2[1][i], wd3);
        }
    }

    // --- Epilogue ---
    float bias4[4];
    #pragma unroll
    for (int j = 0; j < 4; j++) bias4[j] = __ldg(&bias[4 * tx + j]);

    #pragma unroll
    for (int p = 0; p < 2; p++) {
        float lo[4], hi[4];
        #pragma unroll
        for (int j = 0; j < 4; j++) upk2(acc2[p][j], lo[j], hi[j]);
        #pragma unroll
        for (int half = 0; half < 2; half++) {
            int n = ty * 4 + 2 * p + half;
            int v = base + n;
            float4 r;
            float* vals = half ? hi : lo;
            r.x = vals[0] + bias4[0];
            r.y = vals[1] + bias4[1];
            r.z = vals[2] + bias4[2];
            r.w = vals[3] + bias4[3];
            if (RELU_DROP) {
                r.x = fmaxf(r.x, 0.0f); r.y = fmaxf(r.y, 0.0f);
                r.z = fmaxf(r.z, 0.0f); r.w = fmaxf(r.w, 0.0f);
                uint32_t j0 = (uint32_t)(v * D + 4 * tx);
                r.x = (pbits(k0, k1, j0 + 0) & 0x80000000u) ? 0.0f : r.x * 2.0f;
                r.y = (pbits(k0, k1, j0 + 1) & 0x80000000u) ? 0.0f : r.y * 2.0f;
                r.z = (pbits(k0, k1, j0 + 2) & 0x80000000u) ? 0.0f : r.z * 2.0f;
                r.w = (pbits(k0, k1, j0 + 3) & 0x80000000u) ? 0.0f : r.w * 2.0f;
            }
            *reinterpret_cast<float4*>(out + (size_t)v * D + 4 * tx) = r;
        }
    }
}

// ---------------------------------------------------------------------------
// Standalone tiled GEMM (for logits, NC=64):  out[v][c] = A[v] . W[c] + b[c]
// Same microtile scheme; A loaded from global.
// ---------------------------------------------------------------------------
#define GEMM64_SMEM ((128 * 68 + 16 * 256) * 4)

__global__ void __launch_bounds__(128)
gemm64_kernel(const float* __restrict__ A,
              const float* __restrict__ W,
              const float* __restrict__ bias,
              float* __restrict__ out) {
    constexpr int NC = 64, NCP = 68, TXN = 16, NTHR = 128;
    extern __shared__ float sm[];
    float* Wt   = sm;                  // [128][68]
    float* AshF = sm + 128 * NCP;      // [16 pairs][128][2]
    const unsigned long long* AshU =
        reinterpret_cast<const unsigned long long*>(AshF);

    const int tid  = threadIdx.x;
    const int tx   = tid % TXN;
    const int ty   = tid / TXN;
    const int base = blockIdx.x * 32;

    for (int idx = tid; idx < NC * 128; idx += NTHR) {
        int c = idx >> 7, k = idx & 127;
        Wt[k * NCP + c] = W[idx];
    }
    for (int idx = tid; idx < 32 * 128; idx += NTHR) {
        int n = idx >> 7, k = idx & 127;
        AshF[(n >> 1) * 256 + 2 * k + (n & 1)] = A[(size_t)(base + n) * D + k];
    }
    __syncthreads();

    unsigned long long acc2[2][4];
    #pragma unroll
    for (int p = 0; p < 2; p++)
        #pragma unroll
        for (int j = 0; j < 4; j++) acc2[p][j] = 0ull;

    const int p0 = ty * 2;
    #pragma unroll 8
    for (int k = 0; k < 128; k += 4) {
        float4 wv[4];
        #pragma unroll
        for (int i = 0; i < 4; i++)
            wv[i] = *reinterpret_cast<const float4*>(&Wt[(k + i) * NCP + 4 * tx]);
        unsigned long long a2[2][4];
        #pragma unroll
        for (int p = 0; p < 2; p++)
            #pragma unroll
            for (int i = 0; i < 4; i++)
                a2[p][i] = AshU[(p0 + p) * 128 + k + i];
        #pragma unroll
        for (int i = 0; i < 4; i++) {
            unsigned long long wd0 = pk2(wv[i].x, wv[i].x);
            unsigned long long wd1 = pk2(wv[i].y, wv[i].y);
            unsigned long long wd2 = pk2(wv[i].z, wv[i].z);
            unsigned long long wd3 = pk2(wv[i].w, wv[i].w);
            fma2(acc2[0][0], a2[0][i], wd0);
            fma2(acc2[1][0], a2[1][i], wd0);
            fma2(acc2[0][1], a2[0][i], wd1);
            fma2(acc2[1][1], a2[1][i], wd1);
            fma2(acc2[0][2], a2[0][i], wd2);
            fma2(acc2[1][2], a2[1][i], wd2);
            fma2(acc2[0][3], a2[0][i], wd3);
            fma2(acc2[1][3], a2[1][i], wd3);
        }
    }

    float bias4[4];
    #pragma unroll
    for (int j = 0; j < 4; j++) bias4[j] = __ldg(&bias[4 * tx + j]);

    #pragma unroll
    for (int p = 0; p < 2; p++) {
        float lo[4], hi[4];
        #pragma unroll
        for (int j = 0; j < 4; j++) upk2(acc2[p][j], lo[j], hi[j]);
        #pragma unroll
        for (int half = 0; half < 2; half++) {
            int n = ty * 4 + 2 * p + half;
            int v = base + n;
            float4 r;
            float* vals = half ? hi : lo;
            r.x = vals[0] + bias4[0];
            r.y = vals[1] + bias4[1];
            r.z = vals[2] + bias4[2];
            r.w = vals[3] + bias4[3];
            *reinterpret_cast<float4*>(out + (size_t)v * NC + 4 * tx) = r;
        }
    }
}

// ---------------------------------------------------------------------------
// Decoder loss.  One warp per node; lane covers cols (l, l+32).
// ---------------------------------------------------------------------------
__global__ void dec_kernel(const int* __restrict__ shuf) {
    __shared__ float warp_sums[8];
    int warp = threadIdx.x >> 5;
    int lane = threadIdx.x & 31;
    int v = blockIdx.x * 8 + warp;
    float contrib = 0.0f;
    if (v < N_NODES) {
        const float* a = g_logits + (size_t)v * DECD;
        float a0 = a[lane], a1 = a[lane + 32];
        float m = fmaxf(a0, a1);
        #pragma unroll
        for (int off = 16; off; off >>= 1)
            m = fmaxf(m, __shfl_xor_sync(0xffffffffu, m, off));
        float s = expf(a0 - m) + expf(a1 - m);
        #pragma unroll
        for (int off = 16; off; off >>= 1)
            s += __shfl_xor_sync(0xffffffffu, s, off);
        float lse = m + logf(s);
        const float* bp = g_logits + (size_t)__ldg(&shuf[v]) * DECD;
        float b0 = bp[lane], b1 = bp[lane + 32];
        float t = b0 * (a0 - lse) + b1 * (a1 - lse);
        #pragma unroll
        for (int off = 16; off; off >>= 1)
            t += __shfl_xor_sync(0xffffffffu, t, off);
        contrib = -t;
    }
    if (lane == 0) warp_sums[warp] = contrib;
    __syncthreads();
    if (threadIdx.x == 0) {
        float s = 0.0f;
        #pragma unroll
        for (int w = 0; w < 8; w++) s += warp_sums[w];
        atomicAdd(&g_acc, (double)s);
    }
}

__global__ void finalize_kernel(float* __restrict__ out) {
    out[(size_t)N_NODES * D] = (float)(g_acc / (double)N_NODES);
}

// ---------------------------------------------------------------------------
// Host launcher (graph-capturable)
// ---------------------------------------------------------------------------
extern "C" void kernel_launch(void* const* d_in, const int* in_sizes, int n_in,
                              void* d_out, int out_size) {
    const float* x    = (const float*)d_in[0];
    const int*   src  = (const int*)  d_in[1];
    const int*   dst  = (const int*)  d_in[2];
    const int*   shuf = (const int*)  d_in[3];
    const float* W1   = (const float*)d_in[4];
    const float* b1   = (const float*)d_in[5];
    const float* W2   = (const float*)d_in[6];
    const float* b2   = (const float*)d_in[7];
    const float* Wd   = (const float*)d_in[8];
    const float* bd   = (const float*)d_in[9];
    float* out = (float*)d_out;

    // JAX partitionable threefry: split(key(42),2) foldlike.
    uint32_t dk0_k0, dk0_k1, dk1_k0, dk1_k1;
    tf2x32(0u, 42u, 0u, 0u, &dk0_k0, &dk0_k1);   // dropout on x
    tf2x32(0u, 42u, 0u, 1u, &dk1_k0, &dk1_k1);   // dropout after relu(layer1)

    void *p_degi, *p_acc, *p_h0, *p_h1, *p_logits;
    cudaGetSymbolAddress(&p_degi,   g_degi);
    cudaGetSymbolAddress(&p_acc,    g_acc);
    cudaGetSymbolAddress(&p_h0,     g_h0);
    cudaGetSymbolAddress(&p_h1,     g_h1);
    cudaGetSymbolAddress(&p_logits, g_logits);

    cudaFuncSetAttribute((const void*)fused_layer_kernel<1>,
                         cudaFuncAttributeMaxDynamicSharedMemorySize, FUSED_SMEM);
    cudaFuncSetAttribute((const void*)fused_layer_kernel<0>,
                         cudaFuncAttributeMaxDynamicSharedMemorySize, FUSED_SMEM);
    cudaFuncSetAttribute((const void*)gemm64_kernel,
                         cudaFuncAttributeMaxDynamicSharedMemorySize, GEMM64_SMEM);

    // Zero accumulators
    cudaMemsetAsync(p_degi, 0, N_NODES * sizeof(int));
    cudaMemsetAsync(p_acc,  0, sizeof(double));

    // CSR build (reused by both layers)
    deg_kernel<<<(N_EDGES + 255) / 256, 256>>>(dst);
    scan_kernel<<<1, 1024>>>();
    fill_kernel<<<(N_EDGES + 255) / 256, 256>>>(src, dst);

    // h0 = dropout(x, dk0)
    dropout_x_kernel<<<(N_NODES * D / 4 + 255) / 256, 256>>>(x, dk0_k0, dk0_k1);

    // layer 1 (fused gather + GEMM + relu + dropout)
    fused_layer_kernel<1><<<N_NODES / 32, 256, FUSED_SMEM>>>(
        (const float*)p_h0, W1, b1, (float*)p_h1, dk1_k0, dk1_k1);

    // layer 2 (fused gather + GEMM)
    fused_layer_kernel<0><<<N_NODES / 32, 256, FUSED_SMEM>>>(
        (const float*)p_h1, W2, b2, out, 0u, 0u);

    // decoder
    gemm64_kernel<<<N_NODES / 32, 128, GEMM64_SMEM>>>(out, Wd, bd, (float*)p_logits);
    dec_kernel<<<N_NODES / 8, 256>>>(shuf);
    finalize_kernel<<<1, 1>>>(out);
}

// round 8
// speedup vs baseline: 1.5849x; 1.0630x over previous
#include <cuda_runtime.h>
#include <cstdint>

// ---------------------------------------------------------------------------
// Problem constants
// ---------------------------------------------------------------------------
#define N_NODES 40000
#define N_EDGES 640000
#define D       128          // IN = HID = OUT = 128
#define DECD    64
#define TILE    64           // nodes per fused-layer block

// ---------------------------------------------------------------------------
// Scratch (static device globals; no allocations allowed)
// ---------------------------------------------------------------------------
__device__ float  g_h0[N_NODES * D];       // dropout(x)
__device__ float  g_h1[N_NODES * D];       // dropout(relu(layer1))
__device__ float  g_logits[N_NODES * DECD];
__device__ int    g_degi[N_NODES];
__device__ int    g_rowptr[N_NODES + 1];
__device__ int    g_cursor[N_NODES];
__device__ int    g_esrc[N_EDGES];         // CSR-permuted source ids
__device__ double g_acc;
__device__ unsigned int g_ticket;          // self-resetting last-block ticket

// ---------------------------------------------------------------------------
// JAX-exact threefry2x32 (20 rounds), partitionable mode.
// ---------------------------------------------------------------------------
__host__ __device__ __forceinline__ void tf2x32(uint32_t k0, uint32_t k1,
                                                uint32_t x0, uint32_t x1,
                                                uint32_t* o0, uint32_t* o1) {
    uint32_t ks2 = k0 ^ k1 ^ 0x1BD11BDAu;
    x0 += k0; x1 += k1;
#define TF_RND(r) { x0 += x1; x1 = (x1 << (r)) | (x1 >> (32 - (r))); x1 ^= x0; }
    TF_RND(13) TF_RND(15) TF_RND(26) TF_RND(6)   x0 += k1;  x1 += ks2 + 1u;
    TF_RND(17) TF_RND(29) TF_RND(16) TF_RND(24)  x0 += ks2; x1 += k0  + 2u;
    TF_RND(13) TF_RND(15) TF_RND(26) TF_RND(6)   x0 += k0;  x1 += k1  + 3u;
    TF_RND(17) TF_RND(29) TF_RND(16) TF_RND(24)  x0 += k1;  x1 += ks2 + 4u;
    TF_RND(13) TF_RND(15) TF_RND(26) TF_RND(6)   x0 += ks2; x1 += k0  + 5u;
#undef TF_RND
    *o0 = x0; *o1 = x1;
}

// bits = out0 ^ out1 of threefry(key, (0, j)).  keep <=> bit31 == 0.
__device__ __forceinline__ uint32_t pbits(uint32_t k0, uint32_t k1, uint32_t j) {
    uint32_t o0, o1;
    tf2x32(k0, k1, 0u, j, &o0, &o1);
    return o0 ^ o1;
}

// ---------------------------------------------------------------------------
// Packed f32x2 helpers (Blackwell FFMA2)
// ---------------------------------------------------------------------------
__device__ __forceinline__ unsigned long long pk2(float lo, float hi) {
    unsigned long long r;
    asm("mov.b64 %0, {%1, %2};" : "=l"(r) : "f"(lo), "f"(hi));
    return r;
}
__device__ __forceinline__ void upk2(unsigned long long v, float& lo, float& hi) {
    asm("mov.b64 {%0, %1}, %2;" : "=f"(lo), "=f"(hi) : "l"(v));
}
__device__ __forceinline__ void fma2(unsigned long long& d,
                                     unsigned long long a,
                                     unsigned long long b) {
    asm("fma.rn.f32x2 %0, %1, %2, %0;" : "+l"(d) : "l"(a), "l"(b));
}

// ---------------------------------------------------------------------------
// dropout on x -> g_h0
// ---------------------------------------------------------------------------
__global__ void dropout_x_kernel(const float* __restrict__ x,
                                 uint32_t k0, uint32_t k1) {
    int t = blockIdx.x * blockDim.x + threadIdx.x;
    int j = t * 4;
    if (j >= N_NODES * D) return;
    float4 v = *reinterpret_cast<const float4*>(x + j);
    float4 r;
    r.x = (pbits(k0, k1, j + 0) & 0x80000000u) ? 0.0f : v.x * 2.0f;
    r.y = (pbits(k0, k1, j + 1) & 0x80000000u) ? 0.0f : v.y * 2.0f;
    r.z = (pbits(k0, k1, j + 2) & 0x80000000u) ? 0.0f : v.z * 2.0f;
    r.w = (pbits(k0, k1, j + 3) & 0x80000000u) ? 0.0f : v.w * 2.0f;
    *reinterpret_cast<float4*>(g_h0 + j) = r;
}

// ---------------------------------------------------------------------------
// CSR build: degree count, single-block scan, slot fill
// ---------------------------------------------------------------------------
__global__ void deg_kernel(const int* __restrict__ dst) {
    int e = blockIdx.x * blockDim.x + threadIdx.x;
    if (e < N_EDGES) atomicAdd(&g_degi[__ldg(&dst[e])], 1);
}

__global__ void scan_kernel() {
    __shared__ int sh[1024];
    const int tid = threadIdx.x;
    const int per = 40;
    int base = tid * per;
    int s = 0;
    if (base < N_NODES)
        for (int i = 0; i < per; i++) s += g_degi[base + i];
    sh[tid] = s;
    __syncthreads();
    for (int o = 1; o < 1024; o <<= 1) {
        int v = (tid >= o) ? sh[tid - o] : 0;
        __syncthreads();
        sh[tid] += v;
        __syncthreads();
    }
    int run = (tid > 0) ? sh[tid - 1] : 0;
    if (base < N_NODES) {
        for (int i = 0; i < per; i++) {
            int v = base + i;
            g_rowptr[v] = run;
            g_cursor[v] = run;
            run += g_degi[v];
        }
        if (base + per >= N_NODES) g_rowptr[N_NODES] = run;
    }
}

__global__ void fill_kernel(const int* __restrict__ src,
                            const int* __restrict__ dst) {
    int e = blockIdx.x * blockDim.x + threadIdx.x;
    if (e >= N_EDGES) return;
    int d = __ldg(&dst[e]);
    int slot = atomicAdd(&g_cursor[d], 1);
    g_esrc[slot] = __ldg(&src[e]);
}

// ---------------------------------------------------------------------------
// FUSED layer kernel:  out = fc((h[v] + sum_{u->v} h[u]) / (deg+1))
//                       [+ relu + dropout if RELU_DROP]
// Block = 256 threads, TILE=64 nodes.  Phase A: warp-per-8-nodes CSR gather
// into node-pair-interleaved smem.  Phase B: 8-node x 4-col FFMA2 microtile.
// smem: Wt[128][132] (67.6 KB) + Ash[32 pairs][128][2] (32 KB) = 99.6 KB.
// ---------------------------------------------------------------------------
#define FUSED_SMEM ((128 * 132 + 32 * 256) * 4)

template <int RELU_DROP>
__global__ void __launch_bounds__(256, 2)
fused_layer_kernel(const float* __restrict__ h,
                   const float* __restrict__ W,
                   const float* __restrict__ bias,
                   float* __restrict__ out,
                   uint32_t k0, uint32_t k1) {
    extern __shared__ float sm[];
    float* Wt   = sm;                  // [128 k][132]  (Wt[k][c] = W[c][k])
    float* AshF = sm + 128 * 132;      // [32 pairs][128 k][2]
    const unsigned long long* AshU =
        reinterpret_cast<const unsigned long long*>(AshF);

    const int tid  = threadIdx.x;
    const int wid  = tid >> 5;         // 0..7
    const int lane = tid & 31;
    const int base = blockIdx.x * TILE;

    // --- W load: [128 c][128 k] row-major -> transposed padded smem ---
    #pragma unroll
    for (int idx = tid; idx < 128 * 128; idx += 256) {
        int c = idx >> 7, k = idx & 127;
        Wt[k * 132 + c] = W[idx];
    }

    // --- Phase A: 8 nodes per warp; lane covers k = 4*lane..4*lane+3 ---
    #pragma unroll
    for (int nn = 0; nn < 8; nn++) {
        const int n = wid * 8 + nn;
        const int v = base + n;
        const int beg = __ldg(&g_rowptr[v]);
        const int end = __ldg(&g_rowptr[v + 1]);
        float4 acc = *reinterpret_cast<const float4*>(h + (size_t)v * D + lane * 4);
        int i = beg;
        for (; i + 7 < end; i += 8) {
            float4 m[8];
            #pragma unroll
            for (int u = 0; u < 8; u++) {
                int s = __ldg(&g_esrc[i + u]);
                m[u] = *reinterpret_cast<const float4*>(h + (size_t)s * D + lane * 4);
            }
            #pragma unroll
            for (int u = 0; u < 8; u++) {
                acc.x += m[u].x; acc.y += m[u].y;
                acc.z += m[u].z; acc.w += m[u].w;
            }
        }
        for (; i < end; i++) {
            int s = __ldg(&g_esrc[i]);
            float4 m0 = *reinterpret_cast<const float4*>(h + (size_t)s * D + lane * 4);
            acc.x += m0.x; acc.y += m0.y; acc.z += m0.z; acc.w += m0.w;
        }
        float rs = 1.0f / (float)(end - beg + 1);
        acc.x *= rs; acc.y *= rs; acc.z *= rs; acc.w *= rs;
        float* p = AshF + (n >> 1) * 256 + (n & 1);
        p[2 * (4 * lane + 0)] = acc.x;
        p[2 * (4 * lane + 1)] = acc.y;
        p[2 * (4 * lane + 2)] = acc.z;
        p[2 * (4 * lane + 3)] = acc.w;
    }
    __syncthreads();

    // --- Phase B: GEMM.  tx = lane (cols 4*tx..), ty = wid (nodes 8*ty..) ---
    const int tx = lane;
    const int ty = wid;
    unsigned long long acc2[4][4];
    #pragma unroll
    for (int p = 0; p < 4; p++)
        #pragma unroll
        for (int j = 0; j < 4; j++) acc2[p][j] = 0ull;

    const int p0 = ty * 4;             // pair rows p0..p0+3 (nodes 8ty..8ty+7)
    #pragma unroll 4
    for (int k = 0; k < 128; k += 4) {
        float4 wv[4];
        #pragma unroll
        for (int i = 0; i < 4; i++)
            wv[i] = *reinterpret_cast<const float4*>(&Wt[(k + i) * 132 + 4 * tx]);
        #pragma unroll
        for (int i = 0; i < 4; i++) {
            unsigned long long wd0 = pk2(wv[i].x, wv[i].x);
            unsigned long long wd1 = pk2(wv[i].y, wv[i].y);
            unsigned long long wd2 = pk2(wv[i].z, wv[i].z);
            unsigned long long wd3 = pk2(wv[i].w, wv[i].w);
            #pragma unroll
            for (int p = 0; p < 4; p++) {
                unsigned long long av = AshU[(p0 + p) * 128 + k + i];
                fma2(acc2[p][0], av, wd0);
                fma2(acc2[p][1], av, wd1);
                fma2(acc2[p][2], av, wd2);
                fma2(acc2[p][3], av, wd3);
            }
        }
    }

    // --- Epilogue ---
    float bias4[4];
    #pragma unroll
    for (int j = 0; j < 4; j++) bias4[j] = __ldg(&bias[4 * tx + j]);

    #pragma unroll
    for (int p = 0; p < 4; p++) {
        float lo[4], hi[4];
        #pragma unroll
        for (int j = 0; j < 4; j++) upk2(acc2[p][j], lo[j], hi[j]);
        #pragma unroll
        for (int half = 0; half < 2; half++) {
            int n = ty * 8 + 2 * p + half;
            int v = base + n;
            float4 r;
            float* vals = half ? hi : lo;
            r.x = vals[0] + bias4[0];
            r.y = vals[1] + bias4[1];
            r.z = vals[2] + bias4[2];
            r.w = vals[3] + bias4[3];
            if (RELU_DROP) {
                r.x = fmaxf(r.x, 0.0f); r.y = fmaxf(r.y, 0.0f);
                r.z = fmaxf(r.z, 0.0f); r.w = fmaxf(r.w, 0.0f);
                uint32_t j0 = (uint32_t)(v * D + 4 * tx);
                r.x = (pbits(k0, k1, j0 + 0) & 0x80000000u) ? 0.0f : r.x * 2.0f;
                r.y = (pbits(k0, k1, j0 + 1) & 0x80000000u) ? 0.0f : r.y * 2.0f;
                r.z = (pbits(k0, k1, j0 + 2) & 0x80000000u) ? 0.0f : r.z * 2.0f;
                r.w = (pbits(k0, k1, j0 + 3) & 0x80000000u) ? 0.0f : r.w * 2.0f;
            }
            *reinterpret_cast<float4*>(out + (size_t)v * D + 4 * tx) = r;
        }
    }
}

// ---------------------------------------------------------------------------
// Standalone tiled GEMM (logits, NC=64):  out[v][c] = A[v] . W[c] + b[c]
// ---------------------------------------------------------------------------
#define GEMM64_SMEM ((128 * 68 + 16 * 256) * 4)

__global__ void __launch_bounds__(128)
gemm64_kernel(const float* __restrict__ A,
              const float* __restrict__ W,
              const float* __restrict__ bias,
              float* __restrict__ out) {
    constexpr int NC = 64, NCP = 68, TXN = 16, NTHR = 128;
    extern __shared__ float sm[];
    float* Wt   = sm;                  // [128][68]
    float* AshF = sm + 128 * NCP;      // [16 pairs][128][2]
    const unsigned long long* AshU =
        reinterpret_cast<const unsigned long long*>(AshF);

    const int tid  = threadIdx.x;
    const int tx   = tid % TXN;
    const int ty   = tid / TXN;
    const int base = blockIdx.x * 32;

    for (int idx = tid; idx < NC * 128; idx += NTHR) {
        int c = idx >> 7, k = idx & 127;
        Wt[k * NCP + c] = W[idx];
    }
    for (int idx = tid; idx < 32 * 128; idx += NTHR) {
        int n = idx >> 7, k = idx & 127;
        AshF[(n >> 1) * 256 + 2 * k + (n & 1)] = A[(size_t)(base + n) * D + k];
    }
    __syncthreads();

    unsigned long long acc2[2][4];
    #pragma unroll
    for (int p = 0; p < 2; p++)
        #pragma unroll
        for (int j = 0; j < 4; j++) acc2[p][j] = 0ull;

    const int p0 = ty * 2;
    #pragma unroll 8
    for (int k = 0; k < 128; k += 4) {
        float4 wv[4];
        #pragma unroll
        for (int i = 0; i < 4; i++)
            wv[i] = *reinterpret_cast<const float4*>(&Wt[(k + i) * NCP + 4 * tx]);
        #pragma unroll
        for (int i = 0; i < 4; i++) {
            unsigned long long wd0 = pk2(wv[i].x, wv[i].x);
            unsigned long long wd1 = pk2(wv[i].y, wv[i].y);
            unsigned long long wd2 = pk2(wv[i].z, wv[i].z);
            unsigned long long wd3 = pk2(wv[i].w, wv[i].w);
            #pragma unroll
            for (int p = 0; p < 2; p++) {
                unsigned long long av = AshU[(p0 + p) * 128 + k + i];
                fma2(acc2[p][0], av, wd0);
                fma2(acc2[p][1], av, wd1);
                fma2(acc2[p][2], av, wd2);
                fma2(acc2[p][3], av, wd3);
            }
        }
    }

    float bias4[4];
    #pragma unroll
    for (int j = 0; j < 4; j++) bias4[j] = __ldg(&bias[4 * tx + j]);

    #pragma unroll
    for (int p = 0; p < 2; p++) {
        float lo[4], hi[4];
        #pragma unroll
        for (int j = 0; j < 4; j++) upk2(acc2[p][j], lo[j], hi[j]);
        #pragma unroll
        for (int half = 0; half < 2; half++) {
            int n = ty * 4 + 2 * p + half;
            int v = base + n;
            float4 r;
            float* vals = half ? hi : lo;
            r.x = vals[0] + bias4[0];
            r.y = vals[1] + bias4[1];
            r.z = vals[2] + bias4[2];
            r.w = vals[3] + bias4[3];
            *reinterpret_cast<float4*>(out + (size_t)v * NC + 4 * tx) = r;
        }
    }
}

// ---------------------------------------------------------------------------
// Decoder loss + fused finalize (last-block ticket, self-resetting).
// ---------------------------------------------------------------------------
__global__ void dec_kernel(const int* __restrict__ shuf,
                           float* __restrict__ out) {
    __shared__ float warp_sums[8];
    int warp = threadIdx.x >> 5;
    int lane = threadIdx.x & 31;
    int v = blockIdx.x * 8 + warp;
    float contrib = 0.0f;
    if (v < N_NODES) {
        const float* a = g_logits + (size_t)v * DECD;
        float a0 = a[lane], a1 = a[lane + 32];
        float m = fmaxf(a0, a1);
        #pragma unroll
        for (int off = 16; off; off >>= 1)
            m = fmaxf(m, __shfl_xor_sync(0xffffffffu, m, off));
        float s = expf(a0 - m) + expf(a1 - m);
        #pragma unroll
        for (int off = 16; off; off >>= 1)
            s += __shfl_xor_sync(0xffffffffu, s, off);
        float lse = m + logf(s);
        const float* bp = g_logits + (size_t)__ldg(&shuf[v]) * DECD;
        float b0 = bp[lane], b1 = bp[lane + 32];
        float t = b0 * (a0 - lse) + b1 * (a1 - lse);
        #pragma unroll
        for (int off = 16; off; off >>= 1)
            t += __shfl_xor_sync(0xffffffffu, t, off);
        contrib = -t;
    }
    if (lane == 0) warp_sums[warp] = contrib;
    __syncthreads();
    if (threadIdx.x == 0) {
        float s = 0.0f;
        #pragma unroll
        for (int w = 0; w < 8; w++) s += warp_sums[w];
        atomicAdd(&g_acc, (double)s);
        __threadfence();
        unsigned int t = atomicAdd(&g_ticket, 1u);
        if (t == gridDim.x - 1) {
            out[(size_t)N_NODES * D] = (float)(g_acc / (double)N_NODES);
            g_ticket = 0;              // self-reset for graph replay
        }
    }
}

// ---------------------------------------------------------------------------
// Host launcher (graph-capturable).  Launch order puts fused_layer<1> 6th
// so ncu's "-s 5 -c 1" captures it.
// ---------------------------------------------------------------------------
extern "C" void kernel_launch(void* const* d_in, const int* in_sizes, int n_in,
                              void* d_out, int out_size) {
    const float* x    = (const float*)d_in[0];
    const int*   src  = (const int*)  d_in[1];
    const int*   dst  = (const int*)  d_in[2];
    const int*   shuf = (const int*)  d_in[3];
    const float* W1   = (const float*)d_in[4];
    const float* b1   = (const float*)d_in[5];
    const float* W2   = (const float*)d_in[6];
    const float* b2   = (const float*)d_in[7];
    const float* Wd   = (const float*)d_in[8];
    const float* bd   = (const float*)d_in[9];
    float* out = (float*)d_out;

    // JAX partitionable threefry: split(key(42),2) foldlike.
    uint32_t dk0_k0, dk0_k1, dk1_k0, dk1_k1;
    tf2x32(0u, 42u, 0u, 0u, &dk0_k0, &dk0_k1);   // dropout on x
    tf2x32(0u, 42u, 0u, 1u, &dk1_k0, &dk1_k1);   // dropout after relu(layer1)

    void *p_degi, *p_acc, *p_h0, *p_h1, *p_logits;
    cudaGetSymbolAddress(&p_degi,   g_degi);
    cudaGetSymbolAddress(&p_acc,    g_acc);
    cudaGetSymbolAddress(&p_h0,     g_h0);
    cudaGetSymbolAddress(&p_h1,     g_h1);
    cudaGetSymbolAddress(&p_logits, g_logits);

    cudaFuncSetAttribute((const void*)fused_layer_kernel<1>,
                         cudaFuncAttributeMaxDynamicSharedMemorySize, FUSED_SMEM);
    cudaFuncSetAttribute((const void*)fused_layer_kernel<0>,
                         cudaFuncAttributeMaxDynamicSharedMemorySize, FUSED_SMEM);
    cudaFuncSetAttribute((const void*)gemm64_kernel,
                         cudaFuncAttributeMaxDynamicSharedMemorySize, GEMM64_SMEM);

    // 1: zero degree counters
    cudaMemsetAsync(p_degi, 0, N_NODES * sizeof(int));
    // 2: h0 = dropout(x, dk0)
    dropout_x_kernel<<<(N_NODES * D / 4 + 255) / 256, 256>>>(x, dk0_k0, dk0_k1);
    // 3-5: CSR build (reused by both layers)
    deg_kernel<<<(N_EDGES + 255) / 256, 256>>>(dst);
    scan_kernel<<<1, 1024>>>();
    fill_kernel<<<(N_EDGES + 255) / 256, 256>>>(src, dst);
    // 6: layer 1 (fused gather + GEMM + relu + dropout)   <- ncu capture slot
    fused_layer_kernel<1><<<N_NODES / TILE, 256, FUSED_SMEM>>>(
        (const float*)p_h0, W1, b1, (float*)p_h1, dk1_k0, dk1_k1);
    // 7: zero loss accumulator
    cudaMemsetAsync(p_acc, 0, sizeof(double));
    // 8: layer 2 (fused gather + GEMM)
    fused_layer_kernel<0><<<N_NODES / TILE, 256, FUSED_SMEM>>>(
        (const float*)p_h1, W2, b2, out, 0u, 0u);
    // 9: logits
    gemm64_kernel<<<N_NODES / 32, 128, GEMM64_SMEM>>>(out, Wd, bd, (float*)p_logits);
    // 10: decoder loss + finalize
    dec_kernel<<<N_NODES / 8, 256>>>(shuf, out);
}

// round 9
// speedup vs baseline: 1.6941x; 1.0689x over previous
#include <cuda_runtime.h>
#include <cstdint>

// ---------------------------------------------------------------------------
// Problem constants
// ---------------------------------------------------------------------------
#define N_NODES 40000
#define N_EDGES 640000
#define D       128          // IN = HID = OUT = 128
#define DECD    64
#define TILE    64           // nodes per fused-layer block

// ---------------------------------------------------------------------------
// Scratch (static device globals; no allocations allowed)
// ---------------------------------------------------------------------------
__device__ float  g_h0[N_NODES * D];       // dropout(x)
__device__ float  g_h1[N_NODES * D];       // dropout(relu(layer1))
__device__ float  g_logits[N_NODES * DECD];
__device__ int    g_degi[N_NODES];         // zeroed by scan_kernel each pass
__device__ int    g_rowptr[N_NODES + 1];
__device__ int    g_cursor[N_NODES];
__device__ int    g_esrc[N_EDGES];         // CSR-permuted source ids
__device__ double g_acc;                   // reset by dec_kernel each pass
__device__ unsigned int g_ticket;          // self-resetting last-block ticket

// ---------------------------------------------------------------------------
// JAX-exact threefry2x32 (20 rounds), partitionable mode.
// ---------------------------------------------------------------------------
__host__ __device__ __forceinline__ void tf2x32(uint32_t k0, uint32_t k1,
                                                uint32_t x0, uint32_t x1,
                                                uint32_t* o0, uint32_t* o1) {
    uint32_t ks2 = k0 ^ k1 ^ 0x1BD11BDAu;
    x0 += k0; x1 += k1;
#define TF_RND(r) { x0 += x1; x1 = (x1 << (r)) | (x1 >> (32 - (r))); x1 ^= x0; }
    TF_RND(13) TF_RND(15) TF_RND(26) TF_RND(6)   x0 += k1;  x1 += ks2 + 1u;
    TF_RND(17) TF_RND(29) TF_RND(16) TF_RND(24)  x0 += ks2; x1 += k0  + 2u;
    TF_RND(13) TF_RND(15) TF_RND(26) TF_RND(6)   x0 += k0;  x1 += k1  + 3u;
    TF_RND(17) TF_RND(29) TF_RND(16) TF_RND(24)  x0 += k1;  x1 += ks2 + 4u;
    TF_RND(13) TF_RND(15) TF_RND(26) TF_RND(6)   x0 += ks2; x1 += k0  + 5u;
#undef TF_RND
    *o0 = x0; *o1 = x1;
}

// bits = out0 ^ out1 of threefry(key, (0, j)).  keep <=> bit31 == 0.
__device__ __forceinline__ uint32_t pbits(uint32_t k0, uint32_t k1, uint32_t j) {
    uint32_t o0, o1;
    tf2x32(k0, k1, 0u, j, &o0, &o1);
    return o0 ^ o1;
}

// ---------------------------------------------------------------------------
// Packed f32x2 helpers (Blackwell FFMA2)
// ---------------------------------------------------------------------------
__device__ __forceinline__ unsigned long long pk2(float lo, float hi) {
    unsigned long long r;
    asm("mov.b64 %0, {%1, %2};" : "=l"(r) : "f"(lo), "f"(hi));
    return r;
}
__device__ __forceinline__ void upk2(unsigned long long v, float& lo, float& hi) {
    asm("mov.b64 {%0, %1}, %2;" : "=f"(lo), "=f"(hi) : "l"(v));
}
__device__ __forceinline__ void fma2(unsigned long long& d,
                                     unsigned long long a,
                                     unsigned long long b) {
    asm("fma.rn.f32x2 %0, %1, %2, %0;" : "+l"(d) : "l"(a), "l"(b));
}

// ---------------------------------------------------------------------------
// dropout on x -> g_h0
// ---------------------------------------------------------------------------
__global__ void dropout_x_kernel(const float* __restrict__ x,
                                 uint32_t k0, uint32_t k1) {
    int t = blockIdx.x * blockDim.x + threadIdx.x;
    int j = t * 4;
    if (j >= N_NODES * D) return;
    float4 v = *reinterpret_cast<const float4*>(x + j);
    float4 r;
    r.x = (pbits(k0, k1, j + 0) & 0x80000000u) ? 0.0f : v.x * 2.0f;
    r.y = (pbits(k0, k1, j + 1) & 0x80000000u) ? 0.0f : v.y * 2.0f;
    r.z = (pbits(k0, k1, j + 2) & 0x80000000u) ? 0.0f : v.z * 2.0f;
    r.w = (pbits(k0, k1, j + 3) & 0x80000000u) ? 0.0f : v.w * 2.0f;
    *reinterpret_cast<float4*>(g_h0 + j) = r;
}

// ---------------------------------------------------------------------------
// CSR build.  deg/fill: 2 edges per thread (MLP=2 on the atomic chains).
// scan zeroes g_degi after reading -> no memset needed between graph replays.
// ---------------------------------------------------------------------------
__global__ void deg_kernel(const int* __restrict__ dst) {
    int t = blockIdx.x * blockDim.x + threadIdx.x;
    int e0 = t * 2;
    if (e0 >= N_EDGES) return;
    int d0 = __ldg(&dst[e0]);
    int d1 = (e0 + 1 < N_EDGES) ? __ldg(&dst[e0 + 1]) : -1;
    atomicAdd(&g_degi[d0], 1);
    if (d1 >= 0) atomicAdd(&g_degi[d1], 1);
}

__global__ void scan_kernel() {
    __shared__ int sh[1024];
    const int tid = threadIdx.x;
    const int per = 40;
    int base = tid * per;
    int deg_local[per];
    int s = 0;
    if (base < N_NODES) {
        #pragma unroll
        for (int i = 0; i < per; i += 4) {
            int4 d4 = *reinterpret_cast<const int4*>(&g_degi[base + i]);
            deg_local[i + 0] = d4.x; deg_local[i + 1] = d4.y;
            deg_local[i + 2] = d4.z; deg_local[i + 3] = d4.w;
            s += d4.x + d4.y + d4.z + d4.w;
        }
        // zero for next graph replay (only this thread reads these entries)
        int4 z = make_int4(0, 0, 0, 0);
        #pragma unroll
        for (int i = 0; i < per; i += 4)
            *reinterpret_cast<int4*>(&g_degi[base + i]) = z;
    }
    sh[tid] = s;
    __syncthreads();
    for (int o = 1; o < 1024; o <<= 1) {
        int v = (tid >= o) ? sh[tid - o] : 0;
        __syncthreads();
        sh[tid] += v;
        __syncthreads();
    }
    int run = (tid > 0) ? sh[tid - 1] : 0;
    if (base < N_NODES) {
        for (int i = 0; i < per; i++) {
            int v = base + i;
            g_rowptr[v] = run;
            g_cursor[v] = run;
            run += deg_local[i];
        }
        if (base + per >= N_NODES) g_rowptr[N_NODES] = run;
    }
}

__global__ void fill_kernel(const int* __restrict__ src,
                            const int* __restrict__ dst) {
    int t = blockIdx.x * blockDim.x + threadIdx.x;
    int e0 = t * 2;
    if (e0 >= N_EDGES) return;
    int d0 = __ldg(&dst[e0]);
    int s0 = __ldg(&src[e0]);
    int slot0 = atomicAdd(&g_cursor[d0], 1);
    if (e0 + 1 < N_EDGES) {
        int d1 = __ldg(&dst[e0 + 1]);
        int s1 = __ldg(&src[e0 + 1]);
        int slot1 = atomicAdd(&g_cursor[d1], 1);
        g_esrc[slot1] = s1;
    }
    g_esrc[slot0] = s0;
}

// ---------------------------------------------------------------------------
// FUSED layer kernel:  out = fc((h[v] + sum_{u->v} h[u]) / (deg+1))
//                       [+ relu + dropout if RELU_DROP]
// Block = 256 threads, TILE=64 nodes.  Phase A: warp-per-8-nodes CSR gather
// into node-pair-interleaved smem.  Phase B: 8-node x 4-col FFMA2 microtile.
// smem: Wt[128][132] (67.6 KB) + Ash[32 pairs][128][2] (32 KB) = 99.6 KB.
// ---------------------------------------------------------------------------
#define FUSED_SMEM ((128 * 132 + 32 * 256) * 4)

template <int RELU_DROP>
__global__ void __launch_bounds__(256, 2)
fused_layer_kernel(const float* __restrict__ h,
                   const float* __restrict__ W,
                   const float* __restrict__ bias,
                   float* __restrict__ out,
                   uint32_t k0, uint32_t k1) {
    extern __shared__ float sm[];
    float* Wt   = sm;                  // [128 k][132]  (Wt[k][c] = W[c][k])
    float* AshF = sm + 128 * 132;      // [32 pairs][128 k][2]
    const unsigned long long* AshU =
        reinterpret_cast<const unsigned long long*>(AshF);

    const int tid  = threadIdx.x;
    const int wid  = tid >> 5;         // 0..7
    const int lane = tid & 31;
    const int base = blockIdx.x * TILE;

    // --- W load: [128 c][128 k] row-major -> transposed padded smem ---
    #pragma unroll
    for (int idx = tid; idx < 128 * 128; idx += 256) {
        int c = idx >> 7, k = idx & 127;
        Wt[k * 132 + c] = W[idx];
    }

    // --- Phase A: 8 nodes per warp; lane covers k = 4*lane..4*lane+3 ---
    #pragma unroll
    for (int nn = 0; nn < 8; nn++) {
        const int n = wid * 8 + nn;
        const int v = base + n;
        const int beg = __ldg(&g_rowptr[v]);
        const int end = __ldg(&g_rowptr[v + 1]);
        float4 acc = *reinterpret_cast<const float4*>(h + (size_t)v * D + lane * 4);
        int i = beg;
        for (; i + 7 < end; i += 8) {
            float4 m[8];
            #pragma unroll
            for (int u = 0; u < 8; u++) {
                int s = __ldg(&g_esrc[i + u]);
                m[u] = *reinterpret_cast<const float4*>(h + (size_t)s * D + lane * 4);
            }
            #pragma unroll
            for (int u = 0; u < 8; u++) {
                acc.x += m[u].x; acc.y += m[u].y;
                acc.z += m[u].z; acc.w += m[u].w;
            }
        }
        for (; i < end; i++) {
            int s = __ldg(&g_esrc[i]);
            float4 m0 = *reinterpret_cast<const float4*>(h + (size_t)s * D + lane * 4);
            acc.x += m0.x; acc.y += m0.y; acc.z += m0.z; acc.w += m0.w;
        }
        float rs = 1.0f / (float)(end - beg + 1);
        acc.x *= rs; acc.y *= rs; acc.z *= rs; acc.w *= rs;
        float* p = AshF + (n >> 1) * 256 + (n & 1);
        p[2 * (4 * lane + 0)] = acc.x;
        p[2 * (4 * lane + 1)] = acc.y;
        p[2 * (4 * lane + 2)] = acc.z;
        p[2 * (4 * lane + 3)] = acc.w;
    }
    __syncthreads();

    // --- Phase B: GEMM.  tx = lane (cols 4*tx..), ty = wid (nodes 8*ty..) ---
    const int tx = lane;
    const int ty = wid;
    unsigned long long acc2[4][4];
    #pragma unroll
    for (int p = 0; p < 4; p++)
        #pragma unroll
        for (int j = 0; j < 4; j++) acc2[p][j] = 0ull;

    const int p0 = ty * 4;             // pair rows p0..p0+3 (nodes 8ty..8ty+7)
    #pragma unroll 4
    for (int k = 0; k < 128; k += 4) {
        float4 wv[4];
        #pragma unroll
        for (int i = 0; i < 4; i++)
            wv[i] = *reinterpret_cast<const float4*>(&Wt[(k + i) * 132 + 4 * tx]);
        #pragma unroll
        for (int i = 0; i < 4; i++) {
            unsigned long long wd0 = pk2(wv[i].x, wv[i].x);
            unsigned long long wd1 = pk2(wv[i].y, wv[i].y);
            unsigned long long wd2 = pk2(wv[i].z, wv[i].z);
            unsigned long long wd3 = pk2(wv[i].w, wv[i].w);
            #pragma unroll
            for (int p = 0; p < 4; p++) {
                unsigned long long av = AshU[(p0 + p) * 128 + k + i];
                fma2(acc2[p][0], av, wd0);
                fma2(acc2[p][1], av, wd1);
                fma2(acc2[p][2], av, wd2);
                fma2(acc2[p][3], av, wd3);
            }
        }
    }

    // --- Epilogue ---
    float bias4[4];
    #pragma unroll
    for (int j = 0; j < 4; j++) bias4[j] = __ldg(&bias[4 * tx + j]);

    #pragma unroll
    for (int p = 0; p < 4; p++) {
        float lo[4], hi[4];
        #pragma unroll
        for (int j = 0; j < 4; j++) upk2(acc2[p][j], lo[j], hi[j]);
        #pragma unroll
        for (int half = 0; half < 2; half++) {
            int n = ty * 8 + 2 * p + half;
            int v = base + n;
            float4 r;
            float* vals = half ? hi : lo;
            r.x = vals[0] + bias4[0];
            r.y = vals[1] + bias4[1];
            r.z = vals[2] + bias4[2];
            r.w = vals[3] + bias4[3];
            if (RELU_DROP) {
                r.x = fmaxf(r.x, 0.0f); r.y = fmaxf(r.y, 0.0f);
                r.z = fmaxf(r.z, 0.0f); r.w = fmaxf(r.w, 0.0f);
                uint32_t j0 = (uint32_t)(v * D + 4 * tx);
                r.x = (pbits(k0, k1, j0 + 0) & 0x80000000u) ? 0.0f : r.x * 2.0f;
                r.y = (pbits(k0, k1, j0 + 1) & 0x80000000u) ? 0.0f : r.y * 2.0f;
                r.z = (pbits(k0, k1, j0 + 2) & 0x80000000u) ? 0.0f : r.z * 2.0f;
                r.w = (pbits(k0, k1, j0 + 3) & 0x80000000u) ? 0.0f : r.w * 2.0f;
            }
            *reinterpret_cast<float4*>(out + (size_t)v * D + 4 * tx) = r;
        }
    }
}

// ---------------------------------------------------------------------------
// Standalone tiled GEMM (logits, NC=64):  out[v][c] = A[v] . W[c] + b[c]
// ---------------------------------------------------------------------------
#define GEMM64_SMEM ((128 * 68 + 16 * 256) * 4)

__global__ void __launch_bounds__(128)
gemm64_kernel(const float* __restrict__ A,
              const float* __restrict__ W,
              const float* __restrict__ bias,
              float* __restrict__ out) {
    constexpr int NC = 64, NCP = 68, TXN = 16, NTHR = 128;
    extern __shared__ float sm[];
    float* Wt   = sm;                  // [128][68]
    float* AshF = sm + 128 * NCP;      // [16 pairs][128][2]
    const unsigned long long* AshU =
        reinterpret_cast<const unsigned long long*>(AshF);

    const int tid  = threadIdx.x;
    const int tx   = tid % TXN;
    const int ty   = tid / TXN;
    const int base = blockIdx.x * 32;

    for (int idx = tid; idx < NC * 128; idx += NTHR) {
        int c = idx >> 7, k = idx & 127;
        Wt[k * NCP + c] = W[idx];
    }
    for (int idx = tid; idx < 32 * 128; idx += NTHR) {
        int n = idx >> 7, k = idx & 127;
        AshF[(n >> 1) * 256 + 2 * k + (n & 1)] = A[(size_t)(base + n) * D + k];
    }
    __syncthreads();

    unsigned long long acc2[2][4];
    #pragma unroll
    for (int p = 0; p < 2; p++)
        #pragma unroll
        for (int j = 0; j < 4; j++) acc2[p][j] = 0ull;

    const int p0 = ty * 2;
    #pragma unroll 8
    for (int k = 0; k < 128; k += 4) {
        float4 wv[4];
        #pragma unroll
        for (int i = 0; i < 4; i++)
            wv[i] = *reinterpret_cast<const float4*>(&Wt[(k + i) * NCP + 4 * tx]);
        #pragma unroll
        for (int i = 0; i < 4; i++) {
            unsigned long long wd0 = pk2(wv[i].x, wv[i].x);
            unsigned long long wd1 = pk2(wv[i].y, wv[i].y);
            unsigned long long wd2 = pk2(wv[i].z, wv[i].z);
            unsigned long long wd3 = pk2(wv[i].w, wv[i].w);
            #pragma unroll
            for (int p = 0; p < 2; p++) {
                unsigned long long av = AshU[(p0 + p) * 128 + k + i];
                fma2(acc2[p][0], av, wd0);
                fma2(acc2[p][1], av, wd1);
                fma2(acc2[p][2], av, wd2);
                fma2(acc2[p][3], av, wd3);
            }
        }
    }

    float bias4[4];
    #pragma unroll
    for (int j = 0; j < 4; j++) bias4[j] = __ldg(&bias[4 * tx + j]);

    #pragma unroll
    for (int p = 0; p < 2; p++) {
        float lo[4], hi[4];
        #pragma unroll
        for (int j = 0; j < 4; j++) upk2(acc2[p][j], lo[j], hi[j]);
        #pragma unroll
        for (int half = 0; half < 2; half++) {
            int n = ty * 4 + 2 * p + half;
            int v = base + n;
            float4 r;
            float* vals = half ? hi : lo;
            r.x = vals[0] + bias4[0];
            r.y = vals[1] + bias4[1];
            r.z = vals[2] + bias4[2];
            r.w = vals[3] + bias4[3];
            *reinterpret_cast<float4*>(out + (size_t)v * NC + 4 * tx) = r;
        }
    }
}

// ---------------------------------------------------------------------------
// Decoder loss + fused finalize (last-block ticket, self-resetting:
// also resets g_acc for the next graph replay).
// ---------------------------------------------------------------------------
__global__ void dec_kernel(const int* __restrict__ shuf,
                           float* __restrict__ out) {
    __shared__ float warp_sums[8];
    int warp = threadIdx.x >> 5;
    int lane = threadIdx.x & 31;
    int v = blockIdx.x * 8 + warp;
    float contrib = 0.0f;
    if (v < N_NODES) {
        const float* a = g_logits + (size_t)v * DECD;
        float a0 = a[lane], a1 = a[lane + 32];
        float m = fmaxf(a0, a1);
        #pragma unroll
        for (int off = 16; off; off >>= 1)
            m = fmaxf(m, __shfl_xor_sync(0xffffffffu, m, off));
        float s = expf(a0 - m) + expf(a1 - m);
        #pragma unroll
        for (int off = 16; off; off >>= 1)
            s += __shfl_xor_sync(0xffffffffu, s, off);
        float lse = m + logf(s);
        const float* bp = g_logits + (size_t)__ldg(&shuf[v]) * DECD;
        float b0 = bp[lane], b1 = bp[lane + 32];
        float t = b0 * (a0 - lse) + b1 * (a1 - lse);
        #pragma unroll
        for (int off = 16; off; off >>= 1)
            t += __shfl_xor_sync(0xffffffffu, t, off);
        contrib = -t;
    }
    if (lane == 0) warp_sums[warp] = contrib;
    __syncthreads();
    if (threadIdx.x == 0) {
        float s = 0.0f;
        #pragma unroll
        for (int w = 0; w < 8; w++) s += warp_sums[w];
        atomicAdd(&g_acc, (double)s);
        __threadfence();
        unsigned int t = atomicAdd(&g_ticket, 1u);
        if (t == gridDim.x - 1) {
            out[(size_t)N_NODES * D] = (float)(g_acc / (double)N_NODES);
            g_acc = 0.0;               // self-reset for graph replay
            g_ticket = 0;
        }
    }
}

// ---------------------------------------------------------------------------
// Host launcher (graph-capturable).  No memsets; launch order puts
// fused_layer<1> at position 5 so ncu "-s 5 -c 1" captures it.
// ---------------------------------------------------------------------------
extern "C" void kernel_launch(void* const* d_in, const int* in_sizes, int n_in,
                              void* d_out, int out_size) {
    const float* x    = (const float*)d_in[0];
    const int*   src  = (const int*)  d_in[1];
    const int*   dst  = (const int*)  d_in[2];
    const int*   shuf = (const int*)  d_in[3];
    const float* W1   = (const float*)d_in[4];
    const float* b1   = (const float*)d_in[5];
    const float* W2   = (const float*)d_in[6];
    const float* b2   = (const float*)d_in[7];
    const float* Wd   = (const float*)d_in[8];
    const float* bd   = (const float*)d_in[9];
    float* out = (float*)d_out;

    // JAX partitionable threefry: split(key(42),2) foldlike.
    uint32_t dk0_k0, dk0_k1, dk1_k0, dk1_k1;
    tf2x32(0u, 42u, 0u, 0u, &dk0_k0, &dk0_k1);   // dropout on x
    tf2x32(0u, 42u, 0u, 1u, &dk1_k0, &dk1_k1);   // dropout after relu(layer1)

    void *p_h0, *p_h1, *p_logits;
    cudaGetSymbolAddress(&p_h0,     g_h0);
    cudaGetSymbolAddress(&p_h1,     g_h1);
    cudaGetSymbolAddress(&p_logits, g_logits);

    cudaFuncSetAttribute((const void*)fused_layer_kernel<1>,
                         cudaFuncAttributeMaxDynamicSharedMemorySize, FUSED_SMEM);
    cudaFuncSetAttribute((const void*)fused_layer_kernel<0>,
                         cudaFuncAttributeMaxDynamicSharedMemorySize, FUSED_SMEM);
    cudaFuncSetAttribute((const void*)gemm64_kernel,
                         cudaFuncAttributeMaxDynamicSharedMemorySize, GEMM64_SMEM);

    // 1: h0 = dropout(x, dk0)
    dropout_x_kernel<<<(N_NODES * D / 4 + 255) / 256, 256>>>(x, dk0_k0, dk0_k1);
    // 2-4: CSR build (g_degi was zeroed by the previous scan_kernel run)
    deg_kernel<<<(N_EDGES / 2 + 255) / 256, 256>>>(dst);
    scan_kernel<<<1, 1024>>>();
    fill_kernel<<<(N_EDGES / 2 + 255) / 256, 256>>>(src, dst);
    // 5: layer 1 (fused gather + GEMM + relu + dropout)  <- ncu capture slot
    fused_layer_kernel<1><<<N_NODES / TILE, 256, FUSED_SMEM>>>(
        (const float*)p_h0, W1, b1, (float*)p_h1, dk1_k0, dk1_k1);
    // 6: layer 2 (fused gather + GEMM)
    fused_layer_kernel<0><<<N_NODES / TILE, 256, FUSED_SMEM>>>(
        (const float*)p_h1, W2, b2, out, 0u, 0u);
    // 7: logits
    gemm64_kernel<<<N_NODES / 32, 128, GEMM64_SMEM>>>(out, Wd, bd, (float*)p_logits);
    // 8: decoder loss + finalize (self-resets g_acc / g_ticket)
    dec_kernel<<<N_NODES / 8, 256>>>(shuf, out);
}